// round 1
// baseline (speedup 1.0000x reference)
#include <cuda_runtime.h>
#include <math.h>

typedef unsigned long long ull;

#define D        64
#define KCODES   1024
#define KC       64          // codes per chunk
#define MT       128         // rows (vectors) per block
#define NTHREADS 256
#define W        132         // padded smem tile width (floats): 128 data + 4 pad, keeps 16B alignment

// scratch (no cudaMalloc allowed)
__device__ float g_cnorm[KCODES];
__device__ int   g_counts[KCODES];
__device__ float g_loss[2];   // [0] = sum (qst-x)^2, [1] = sum (q-x)^2

__device__ __forceinline__ ull pack2(float lo, float hi) {
    ull r;
    asm("mov.b64 %0, {%1, %2};" : "=l"(r) : "f"(lo), "f"(hi));
    return r;
}
__device__ __forceinline__ ull fma2(ull a, ull b, ull c) {
    ull d;
    asm("fma.rn.f32x2 %0, %1, %2, %3;" : "=l"(d) : "l"(a), "l"(b), "l"(c));
    return d;
}
__device__ __forceinline__ float lo32(ull v) { return __uint_as_float((unsigned)(v & 0xffffffffull)); }
__device__ __forceinline__ float hi32(ull v) { return __uint_as_float((unsigned)(v >> 32)); }

// ---------------------------------------------------------------------------
// prep: codebook norms, zero scratch
// ---------------------------------------------------------------------------
__global__ void vq_prep(const float* __restrict__ cb) {
    int k = blockIdx.x * blockDim.x + threadIdx.x;
    if (k < KCODES) {
        const float* c = cb + (size_t)k * D;
        float s = 0.f;
        #pragma unroll
        for (int d = 0; d < D; d++) s = fmaf(c[d], c[d], s);
        g_cnorm[k]  = s;
        g_counts[k] = 0;
    }
    if (k < 2) g_loss[k] = 0.f;
}

// ---------------------------------------------------------------------------
// main: fused distance-argmin + quantize + ST output + loss/count partials
// block: 256 threads, 128 rows x 1024 codes; chunked 64 codes at a time.
// thread micro-tile: 8 rows x 4 cols via packed f32x2 FMA (rows packed in pairs,
// code values duplicate-stored in smem so the dup operand is a plain 8B LDS).
// ---------------------------------------------------------------------------
__global__ void __launch_bounds__(NTHREADS)
vq_main(const float* __restrict__ xin, const float* __restrict__ cb,
        float* __restrict__ outq, float* __restrict__ outt) {
    extern __shared__ float smem[];
    float* sx  = smem;               // [D][W] transposed x tile (d-major)
    float* sc  = smem + D * W;       // [D][W] transposed, duplicated code chunk
    float* scn = smem + 2 * D * W;   // [KC] code norms of chunk

    const int tid  = threadIdx.x;
    const int lane = tid & 31;
    const int warp = tid >> 5;
    const int hl   = lane & 15;           // lane within 16-lane half
    const int half = lane >> 4;
    const int rowgrp = (warp << 1) | half;    // 0..15 -> 8 rows each
    const int colgrp = hl;                    // 0..15 -> 4 cols each
    const int rb = rowgrp * 8;                // local row base
    const int row0 = blockIdx.x * MT;

    // ---- load x tile transposed (coalesced global read) ----
    #pragma unroll
    for (int t = 0; t < (MT * D) / NTHREADS; t++) {
        int lin = t * NTHREADS + tid;
        int r = lin >> 6;
        int d = lin & 63;
        sx[d * W + r] = xin[(size_t)row0 * D + lin];
    }
    __syncthreads();

    // ---- |x|^2 for my 8 rows (16-lane cooperative) ----
    float xn[8];
    #pragma unroll
    for (int i = 0; i < 8; i++) {
        int r = rb + i;
        float a0 = sx[(hl)      * W + r];
        float a1 = sx[(hl + 16) * W + r];
        float a2 = sx[(hl + 32) * W + r];
        float a3 = sx[(hl + 48) * W + r];
        float s = a0 * a0 + a1 * a1 + a2 * a2 + a3 * a3;
        s += __shfl_xor_sync(0xffffffffu, s, 8);
        s += __shfl_xor_sync(0xffffffffu, s, 4);
        s += __shfl_xor_sync(0xffffffffu, s, 2);
        s += __shfl_xor_sync(0xffffffffu, s, 1);
        xn[i] = s;
    }

    float bd[8];
    int   bi[8];
    #pragma unroll
    for (int i = 0; i < 8; i++) { bd[i] = 3.4e38f; bi[i] = 0; }

    // ---- chunk loop over codebook ----
    for (int ck = 0; ck < KCODES / KC; ck++) {
        const int kbase = ck * KC;
        __syncthreads();
        #pragma unroll
        for (int t = 0; t < (KC * D) / NTHREADS; t++) {
            int lin = t * NTHREADS + tid;
            int kc = lin >> 6;
            int d  = lin & 63;
            float v = cb[(size_t)(kbase + kc) * D + d];
            *(ull*)&sc[d * W + 2 * kc] = pack2(v, v);   // duplicate-store
        }
        if (tid < KC) scn[tid] = g_cnorm[kbase + tid];
        __syncthreads();

        ull acc[4][4];
        #pragma unroll
        for (int p = 0; p < 4; p++)
            #pragma unroll
            for (int c = 0; c < 4; c++) acc[p][c] = 0ull;

        #pragma unroll 8
        for (int d = 0; d < D; d++) {
            const float* xrow = &sx[d * W + rb];
            ull x0 = *(const ull*)(xrow + 0);
            ull x1 = *(const ull*)(xrow + 2);
            ull x2 = *(const ull*)(xrow + 4);
            ull x3 = *(const ull*)(xrow + 6);
            const float* crow = &sc[d * W + colgrp * 8];
            ull c0 = *(const ull*)(crow + 0);
            ull c1 = *(const ull*)(crow + 2);
            ull c2 = *(const ull*)(crow + 4);
            ull c3 = *(const ull*)(crow + 6);
            acc[0][0] = fma2(x0, c0, acc[0][0]);
            acc[0][1] = fma2(x0, c1, acc[0][1]);
            acc[0][2] = fma2(x0, c2, acc[0][2]);
            acc[0][3] = fma2(x0, c3, acc[0][3]);
            acc[1][0] = fma2(x1, c0, acc[1][0]);
            acc[1][1] = fma2(x1, c1, acc[1][1]);
            acc[1][2] = fma2(x1, c2, acc[1][2]);
            acc[1][3] = fma2(x1, c3, acc[1][3]);
            acc[2][0] = fma2(x2, c0, acc[2][0]);
            acc[2][1] = fma2(x2, c1, acc[2][1]);
            acc[2][2] = fma2(x2, c2, acc[2][2]);
            acc[2][3] = fma2(x2, c3, acc[2][3]);
            acc[3][0] = fma2(x3, c0, acc[3][0]);
            acc[3][1] = fma2(x3, c1, acc[3][1]);
            acc[3][2] = fma2(x3, c2, acc[3][2]);
            acc[3][3] = fma2(x3, c3, acc[3][3]);
        }

        // distances (reference add order) + running argmin, k ascending
        #pragma unroll
        for (int c = 0; c < 4; c++) {
            int   k  = kbase + colgrp * 4 + c;
            float cn = scn[colgrp * 4 + c];
            #pragma unroll
            for (int p = 0; p < 4; p++) {
                float s0 = lo32(acc[p][c]);
                float s1 = hi32(acc[p][c]);
                float d0 = (xn[2 * p]     + cn) - 2.f * s0;
                float d1 = (xn[2 * p + 1] + cn) - 2.f * s1;
                if (d0 < bd[2 * p])     { bd[2 * p]     = d0; bi[2 * p]     = k; }
                if (d1 < bd[2 * p + 1]) { bd[2 * p + 1] = d1; bi[2 * p + 1] = k; }
            }
        }
    }

    // ---- argmin reduce across the 16-lane col group (tie -> lower index) ----
    #pragma unroll
    for (int i = 0; i < 8; i++) {
        float d = bd[i];
        int   b = bi[i];
        #pragma unroll
        for (int off = 8; off >= 1; off >>= 1) {
            float od = __shfl_xor_sync(0xffffffffu, d, off);
            int   ob = __shfl_xor_sync(0xffffffffu, b, off);
            if (od < d || (od == d && ob < b)) { d = od; b = ob; }
        }
        bd[i] = d;
        bi[i] = b;
    }

    // ---- epilogue: tokens, quantized_st, loss & usage partials ----
    float e_acc = 0.f, q_acc = 0.f;
    #pragma unroll
    for (int i = 0; i < 8; i++) {
        int row = row0 + rb + i;
        int b   = bi[i];
        if (hl == 0) {
            outt[row] = (float)b;
            atomicAdd(&g_counts[b], 1);
        }
        float4 q4 = *(const float4*)&cb[(size_t)b * D + hl * 4];
        float4 x4 = *(const float4*)&xin[(size_t)row * D + hl * 4];
        float t0 = q4.x - x4.x, t1 = q4.y - x4.y, t2 = q4.z - x4.z, t3 = q4.w - x4.w;
        float4 o;
        o.x = x4.x + t0; o.y = x4.y + t1; o.z = x4.z + t2; o.w = x4.w + t3;
        *(float4*)&outq[(size_t)row * D + hl * 4] = o;
        float e0 = o.x - x4.x, e1 = o.y - x4.y, e2 = o.z - x4.z, e3 = o.w - x4.w;
        e_acc += e0 * e0 + e1 * e1 + e2 * e2 + e3 * e3;
        q_acc += t0 * t0 + t1 * t1 + t2 * t2 + t3 * t3;
    }
    #pragma unroll
    for (int off = 16; off >= 1; off >>= 1) {
        e_acc += __shfl_xor_sync(0xffffffffu, e_acc, off);
        q_acc += __shfl_xor_sync(0xffffffffu, q_acc, off);
    }
    if (lane == 0) {
        atomicAdd(&g_loss[0], e_acc);
        atomicAdd(&g_loss[1], q_acc);
    }
}

// ---------------------------------------------------------------------------
// finalize: losses + perplexity -> 4 scalars
// ---------------------------------------------------------------------------
__global__ void vq_fin(float* __restrict__ outs, float inv_ND, float invN) {
    __shared__ float sh[256];
    float h = 0.f;
    for (int k = threadIdx.x; k < KCODES; k += 256) {
        float p = (float)g_counts[k] * invN;
        h += p * logf(p + 1e-10f);
    }
    sh[threadIdx.x] = h;
    __syncthreads();
    for (int s = 128; s > 0; s >>= 1) {
        if (threadIdx.x < s) sh[threadIdx.x] += sh[threadIdx.x + s];
        __syncthreads();
    }
    if (threadIdx.x == 0) {
        float Le = g_loss[0] * inv_ND;
        float Lq = g_loss[1] * inv_ND;
        float commitment = 0.25f * Le;       // COMMITMENT_COST
        outs[0] = commitment + Lq;           // vq_loss
        outs[1] = commitment;                // commitment_loss
        outs[2] = Lq;                        // codebook_loss
        outs[3] = expf(-sh[0]);              // perplexity
    }
}

extern "C" void kernel_launch(void* const* d_in, const int* in_sizes, int n_in,
                              void* d_out, int out_size) {
    const float* x  = (const float*)d_in[0];
    const float* cb = (const float*)d_in[1];
    float* out = (float*)d_out;

    const int ND = in_sizes[0];       // N * D
    const int N  = ND / D;            // 262144

    float* outq = out;                // quantized_st, ND floats
    float* outt = out + ND;           // tokens (as float), N floats
    float* outs = out + ND + N;       // vq_loss, commitment, codebook, perplexity

    const int smem_bytes = (2 * D * W + KC) * (int)sizeof(float);  // ~67.8 KB
    cudaFuncSetAttribute(vq_main, cudaFuncAttributeMaxDynamicSharedMemorySize, smem_bytes);

    vq_prep<<<(KCODES + 255) / 256, 256>>>(cb);
    vq_main<<<N / MT, NTHREADS, smem_bytes>>>(x, cb, outq, outt);
    vq_fin<<<1, 256>>>(outs, 1.f / (float)ND, 1.f / (float)N);
}

// round 2
// speedup vs baseline: 1.2619x; 1.2619x over previous
#include <cuda_runtime.h>
#include <math.h>

typedef unsigned long long ull;

#define D        64
#define KCODES   1024
#define KC       64          // codes per chunk
#define MT       128         // rows (vectors) per block
#define NTHREADS 256
#define W        132         // padded smem tile width (floats), 16B-aligned rows

// scratch (no cudaMalloc allowed)
__device__ int   g_counts[KCODES];
__device__ float g_loss[2];   // [0] = sum (qst-x)^2, [1] = sum (q-x)^2
__device__ unsigned g_done;

__device__ __forceinline__ ull pack2(float lo, float hi) {
    ull r;
    asm("mov.b64 %0, {%1, %2};" : "=l"(r) : "f"(lo), "f"(hi));
    return r;
}
__device__ __forceinline__ ull fma2(ull a, ull b, ull c) {
    ull d;
    asm("fma.rn.f32x2 %0, %1, %2, %3;" : "=l"(d) : "l"(a), "l"(b), "l"(c));
    return d;
}
__device__ __forceinline__ float lo32(ull v) { return __uint_as_float((unsigned)(v & 0xffffffffull)); }
__device__ __forceinline__ float hi32(ull v) { return __uint_as_float((unsigned)(v >> 32)); }

// ---------------------------------------------------------------------------
// single fused kernel: distance GEMM + argmin + quantize(ST) + losses +
// counts; last block finalizes the 4 scalars and resets scratch for the
// next graph replay.
// block: 256 threads, 128 rows x 1024 codes; chunked 64 codes at a time.
// thread micro-tile: 8 rows x 4 cols via packed f32x2 FMA. Code values are
// duplicate-stored; lane hl owns codes {c*16+hl} so each c-side LDS.64 has
// lanes at 8B stride over one 128B row => conflict-free.
// ---------------------------------------------------------------------------
__global__ void __launch_bounds__(NTHREADS)
vq_fused(const float* __restrict__ xin, const float* __restrict__ cb,
         float* __restrict__ outq, float* __restrict__ outt,
         float* __restrict__ outs, float inv_ND, float invN) {
    extern __shared__ float smem[];
    float* sx  = smem;               // [D][W] transposed x tile (d-major)
    float* sc  = smem + D * W;       // [D][W] transposed, duplicated code chunk
    float* scn = smem + 2 * D * W;   // [KC] code norms of chunk
    __shared__ int s_last;

    const int tid  = threadIdx.x;
    const int lane = tid & 31;
    const int warp = tid >> 5;
    const int hl   = lane & 15;              // lane within 16-lane half
    const int half = lane >> 4;
    const int rowgrp = (warp << 1) | half;   // 0..15 -> 8 rows each
    const int rb = rowgrp * 8;               // local row base
    const int row0 = blockIdx.x * MT;

    // ---- load x tile transposed (coalesced global read) ----
    #pragma unroll
    for (int t = 0; t < (MT * D) / NTHREADS; t++) {
        int lin = t * NTHREADS + tid;
        int r = lin >> 6;
        int d = lin & 63;
        sx[d * W + r] = xin[(size_t)row0 * D + lin];
    }
    __syncthreads();

    // ---- |x|^2 for my 8 rows (16-lane cooperative) ----
    float xn[8];
    #pragma unroll
    for (int i = 0; i < 8; i++) {
        int r = rb + i;
        float a0 = sx[(hl)      * W + r];
        float a1 = sx[(hl + 16) * W + r];
        float a2 = sx[(hl + 32) * W + r];
        float a3 = sx[(hl + 48) * W + r];
        float s = a0 * a0 + a1 * a1 + a2 * a2 + a3 * a3;
        s += __shfl_xor_sync(0xffffffffu, s, 8);
        s += __shfl_xor_sync(0xffffffffu, s, 4);
        s += __shfl_xor_sync(0xffffffffu, s, 2);
        s += __shfl_xor_sync(0xffffffffu, s, 1);
        xn[i] = s;
    }

    float bd[8];
    int   bi[8];
    #pragma unroll
    for (int i = 0; i < 8; i++) { bd[i] = 3.4e38f; bi[i] = 0; }

    // ---- chunk loop over codebook ----
    for (int ck = 0; ck < KCODES / KC; ck++) {
        const int kbase = ck * KC;
        __syncthreads();
        #pragma unroll
        for (int t = 0; t < (KC * D) / NTHREADS; t++) {
            int lin = t * NTHREADS + tid;
            int kc = lin >> 6;
            int d  = lin & 63;
            float v = cb[(size_t)(kbase + kc) * D + d];
            *(ull*)&sc[d * W + 2 * kc] = pack2(v, v);   // duplicate-store
        }
        // per-chunk code norms (redundant per block, trivial cost; L1/L2 hit)
        if (tid < KC) {
            const float* c = cb + (size_t)(kbase + tid) * D;
            float s = 0.f;
            #pragma unroll
            for (int q = 0; q < D / 4; q++) {
                float4 v = *(const float4*)(c + 4 * q);
                s = fmaf(v.x, v.x, fmaf(v.y, v.y, fmaf(v.z, v.z, fmaf(v.w, v.w, s))));
            }
            scn[tid] = s;
        }
        __syncthreads();

        ull acc[4][4];
        #pragma unroll
        for (int p = 0; p < 4; p++)
            #pragma unroll
            for (int c = 0; c < 4; c++) acc[p][c] = 0ull;

        #pragma unroll 8
        for (int d = 0; d < D; d++) {
            const float* xrow = &sx[d * W + rb];
            ulonglong2 xa = *(const ulonglong2*)(xrow);      // rows 0-3 (packed pairs)
            ulonglong2 xb = *(const ulonglong2*)(xrow + 4);  // rows 4-7
            const float* crow = &sc[d * W + 2 * hl];
            ull c0 = *(const ull*)(crow);          // code hl       (8B-stride lanes: conflict-free)
            ull c1 = *(const ull*)(crow + 32);     // code hl + 16
            ull c2 = *(const ull*)(crow + 64);     // code hl + 32
            ull c3 = *(const ull*)(crow + 96);     // code hl + 48
            acc[0][0] = fma2(xa.x, c0, acc[0][0]);
            acc[0][1] = fma2(xa.x, c1, acc[0][1]);
            acc[0][2] = fma2(xa.x, c2, acc[0][2]);
            acc[0][3] = fma2(xa.x, c3, acc[0][3]);
            acc[1][0] = fma2(xa.y, c0, acc[1][0]);
            acc[1][1] = fma2(xa.y, c1, acc[1][1]);
            acc[1][2] = fma2(xa.y, c2, acc[1][2]);
            acc[1][3] = fma2(xa.y, c3, acc[1][3]);
            acc[2][0] = fma2(xb.x, c0, acc[2][0]);
            acc[2][1] = fma2(xb.x, c1, acc[2][1]);
            acc[2][2] = fma2(xb.x, c2, acc[2][2]);
            acc[2][3] = fma2(xb.x, c3, acc[2][3]);
            acc[3][0] = fma2(xb.y, c0, acc[3][0]);
            acc[3][1] = fma2(xb.y, c1, acc[3][1]);
            acc[3][2] = fma2(xb.y, c2, acc[3][2]);
            acc[3][3] = fma2(xb.y, c3, acc[3][3]);
        }

        // distances (reference add order) + running argmin; per-thread visit
        // order is k-ascending within its subset, strict < keeps lowest index
        #pragma unroll
        for (int c = 0; c < 4; c++) {
            int   k  = kbase + c * 16 + hl;
            float cn = scn[c * 16 + hl];
            #pragma unroll
            for (int p = 0; p < 4; p++) {
                float s0 = lo32(acc[p][c]);
                float s1 = hi32(acc[p][c]);
                float d0 = (xn[2 * p]     + cn) - 2.f * s0;
                float d1 = (xn[2 * p + 1] + cn) - 2.f * s1;
                if (d0 < bd[2 * p])     { bd[2 * p]     = d0; bi[2 * p]     = k; }
                if (d1 < bd[2 * p + 1]) { bd[2 * p + 1] = d1; bi[2 * p + 1] = k; }
            }
        }
    }

    // ---- argmin reduce across the 16-lane col group (tie -> lower index) ----
    #pragma unroll
    for (int i = 0; i < 8; i++) {
        float d = bd[i];
        int   b = bi[i];
        #pragma unroll
        for (int off = 8; off >= 1; off >>= 1) {
            float od = __shfl_xor_sync(0xffffffffu, d, off);
            int   ob = __shfl_xor_sync(0xffffffffu, b, off);
            if (od < d || (od == d && ob < b)) { d = od; b = ob; }
        }
        bd[i] = d;
        bi[i] = b;
    }

    // ---- epilogue: tokens, quantized_st, loss & usage partials ----
    float e_acc = 0.f, q_acc = 0.f;
    #pragma unroll
    for (int i = 0; i < 8; i++) {
        int row = row0 + rb + i;
        int b   = bi[i];
        if (hl == 0) {
            outt[row] = (float)b;
            atomicAdd(&g_counts[b], 1);
        }
        float4 q4 = *(const float4*)&cb[(size_t)b * D + hl * 4];
        float4 x4 = *(const float4*)&xin[(size_t)row * D + hl * 4];
        float t0 = q4.x - x4.x, t1 = q4.y - x4.y, t2 = q4.z - x4.z, t3 = q4.w - x4.w;
        float4 o;
        o.x = x4.x + t0; o.y = x4.y + t1; o.z = x4.z + t2; o.w = x4.w + t3;
        *(float4*)&outq[(size_t)row * D + hl * 4] = o;
        float e0 = o.x - x4.x, e1 = o.y - x4.y, e2 = o.z - x4.z, e3 = o.w - x4.w;
        e_acc += e0 * e0 + e1 * e1 + e2 * e2 + e3 * e3;
        q_acc += t0 * t0 + t1 * t1 + t2 * t2 + t3 * t3;
    }
    #pragma unroll
    for (int off = 16; off >= 1; off >>= 1) {
        e_acc += __shfl_xor_sync(0xffffffffu, e_acc, off);
        q_acc += __shfl_xor_sync(0xffffffffu, q_acc, off);
    }
    if (lane == 0) {
        atomicAdd(&g_loss[0], e_acc);
        atomicAdd(&g_loss[1], q_acc);
    }

    // ---- last-block finalize (4 scalars) + scratch reset for next replay ----
    __threadfence();
    __syncthreads();
    if (tid == 0) {
        unsigned t = atomicAdd(&g_done, 1u);
        s_last = (t == gridDim.x - 1) ? 1 : 0;
    }
    __syncthreads();
    if (s_last) {
        float h = 0.f;
        for (int k = tid; k < KCODES; k += NTHREADS) {
            float p = (float)g_counts[k] * invN;
            h += p * logf(p + 1e-10f);
        }
        // block reduce via smem (reuse sx)
        sx[tid] = h;
        __syncthreads();
        for (int s = NTHREADS / 2; s > 0; s >>= 1) {
            if (tid < s) sx[tid] += sx[tid + s];
            __syncthreads();
        }
        if (tid == 0) {
            float Le = g_loss[0] * inv_ND;
            float Lq = g_loss[1] * inv_ND;
            float commitment = 0.25f * Le;       // COMMITMENT_COST
            outs[0] = commitment + Lq;           // vq_loss
            outs[1] = commitment;                // commitment_loss
            outs[2] = Lq;                        // codebook_loss
            outs[3] = expf(-sx[0]);              // perplexity
            g_loss[0] = 0.f;
            g_loss[1] = 0.f;
            g_done = 0u;
        }
        __syncthreads();
        for (int k = tid; k < KCODES; k += NTHREADS) g_counts[k] = 0;
    }
}

extern "C" void kernel_launch(void* const* d_in, const int* in_sizes, int n_in,
                              void* d_out, int out_size) {
    const float* x  = (const float*)d_in[0];
    const float* cb = (const float*)d_in[1];
    float* out = (float*)d_out;

    const int ND = in_sizes[0];       // N * D
    const int N  = ND / D;            // 262144

    float* outq = out;                // quantized_st, ND floats
    float* outt = out + ND;           // tokens (as float), N floats
    float* outs = out + ND + N;       // vq_loss, commitment, codebook, perplexity

    const int smem_bytes = (2 * D * W + KC) * (int)sizeof(float);  // ~67.8 KB
    cudaFuncSetAttribute(vq_fused, cudaFuncAttributeMaxDynamicSharedMemorySize, smem_bytes);

    vq_fused<<<N / MT, NTHREADS, smem_bytes>>>(x, cb, outq, outt, outs,
                                               1.f / (float)ND, 1.f / (float)N);
}

// round 6
// speedup vs baseline: 1.3342x; 1.0573x over previous
#include <cuda_runtime.h>
#include <math.h>

typedef unsigned long long ull;

#define D        64
#define KCODES   1024
#define KC       128         // codes per chunk
#define MT       128         // rows (vectors) per block
#define NTHREADS 256
#define W2       268         // dup-x tile row width (floats): 256 data + 12 pad; 268%4==0 -> 16B-aligned rows
#define W3       130         // code tile row width (floats): 128 data + 2 pad; 8B-aligned rows

// scratch (no cudaMalloc allowed)
__device__ int   g_counts[KCODES];
__device__ float g_loss[2];   // [0] = sum (qst-x)^2, [1] = sum (q-x)^2
__device__ unsigned g_done;

__device__ __forceinline__ ull pack2(float lo, float hi) {
    ull r;
    asm("mov.b64 %0, {%1, %2};" : "=l"(r) : "f"(lo), "f"(hi));
    return r;
}
__device__ __forceinline__ ull fma2(ull a, ull b, ull c) {
    ull d;
    asm("fma.rn.f32x2 %0, %1, %2, %3;" : "=l"(d) : "l"(a), "l"(b), "l"(c));
    return d;
}
__device__ __forceinline__ float lo32(ull v) { return __uint_as_float((unsigned)(v & 0xffffffffull)); }
__device__ __forceinline__ float hi32(ull v) { return __uint_as_float((unsigned)(v >> 32)); }

// ---------------------------------------------------------------------------
// fused: distance GEMM + argmin + quantize(ST) + losses + counts + finalize.
// block: 256 threads, 128 rows; codebook chunked 128 codes at a time.
// thread micro-tile: 8 rows x 8 codes. x is duplicate-stored ({v,v} pairs) so
// 4 LDS.128 yield 8 broadcast-ready row operands; codes stay natural so each
// LDS.64 fetches an adjacent code PAIR (lo/hi lanes of the packed FMA).
// 32 f32x2 FMAs per d-iter against ~8 crossbar wavefronts -> FMA-pipe bound.
// ---------------------------------------------------------------------------
__global__ void __launch_bounds__(NTHREADS, 1)
vq_fused(const float* __restrict__ xin, const float* __restrict__ cb,
         float* __restrict__ outq, float* __restrict__ outt,
         float* __restrict__ outs, float inv_ND, float invN) {
    extern __shared__ float smem[];
    float* sx2 = smem;               // [D][W2] dup-stored x tile (d-major)
    float* sc  = smem + D * W2;      // [D][W3] code chunk, natural (d-major)
    float* scn = smem + D * W2 + D * W3;  // [KC] code norms of chunk
    __shared__ int s_last;

    const int tid  = threadIdx.x;
    const int lane = tid & 31;
    const int warp = tid >> 5;
    const int hl   = lane & 15;              // colgrp: 8 codes {2*(j*16+hl)+0/1}
    const int half = lane >> 4;
    const int rowgrp = (warp << 1) | half;   // 0..15 -> 8 rows each
    const int rb = rowgrp * 8;               // local row base
    const int row0 = blockIdx.x * MT;

    // ---- load x tile, duplicate-stored transposed (coalesced global read) ----
    #pragma unroll
    for (int t = 0; t < (MT * D) / NTHREADS; t++) {
        int lin = t * NTHREADS + tid;
        int r = lin >> 6;
        int d = lin & 63;
        float v = xin[(size_t)row0 * D + lin];
        *(ull*)&sx2[d * W2 + 2 * r] = pack2(v, v);
    }
    __syncthreads();

    // ---- |x|^2 for my 8 rows (16-lane cooperative over d) ----
    float xn[8];
    #pragma unroll
    for (int i = 0; i < 8; i++) {
        int r = rb + i;
        float a0 = sx2[(hl)      * W2 + 2 * r];
        float a1 = sx2[(hl + 16) * W2 + 2 * r];
        float a2 = sx2[(hl + 32) * W2 + 2 * r];
        float a3 = sx2[(hl + 48) * W2 + 2 * r];
        float s = a0 * a0 + a1 * a1 + a2 * a2 + a3 * a3;
        s += __shfl_xor_sync(0xffffffffu, s, 8);
        s += __shfl_xor_sync(0xffffffffu, s, 4);
        s += __shfl_xor_sync(0xffffffffu, s, 2);
        s += __shfl_xor_sync(0xffffffffu, s, 1);
        xn[i] = s;
    }

    float bd[8];
    int   bi[8];
    #pragma unroll
    for (int i = 0; i < 8; i++) { bd[i] = 3.4e38f; bi[i] = 0; }

    // ---- chunk loop over codebook ----
    for (int ck = 0; ck < KCODES / KC; ck++) {
        const int kbase = ck * KC;
        __syncthreads();
        #pragma unroll
        for (int t = 0; t < (KC * D) / NTHREADS; t++) {
            int lin = t * NTHREADS + tid;
            int kc = lin >> 6;
            int d  = lin & 63;
            sc[d * W3 + kc] = cb[(size_t)(kbase + kc) * D + d];
        }
        // per-chunk code norms (cheap, hits L1/L2)
        if (tid < KC) {
            const float* c = cb + (size_t)(kbase + tid) * D;
            float s = 0.f;
            #pragma unroll
            for (int q = 0; q < D / 4; q++) {
                float4 v = *(const float4*)(c + 4 * q);
                s = fmaf(v.x, v.x, fmaf(v.y, v.y, fmaf(v.z, v.z, fmaf(v.w, v.w, s))));
            }
            scn[tid] = s;
        }
        __syncthreads();

        ull acc[8][4];
        #pragma unroll
        for (int r = 0; r < 8; r++)
            #pragma unroll
            for (int j = 0; j < 4; j++) acc[r][j] = 0ull;

        #pragma unroll 4
        for (int d = 0; d < D; d++) {
            const float* xrow = &sx2[d * W2 + 2 * rb];     // 8 dup'd rows = 16 floats, 16B-aligned
            ulonglong2 xA = *(const ulonglong2*)(xrow);     // {x0,x0},{x1,x1}
            ulonglong2 xB = *(const ulonglong2*)(xrow + 4);
            ulonglong2 xC = *(const ulonglong2*)(xrow + 8);
            ulonglong2 xD = *(const ulonglong2*)(xrow + 12);
            const float* crow = &sc[d * W3 + 2 * hl];
            ull c0 = *(const ull*)(crow);        // codes {2hl, 2hl+1}  (lanes 8B stride: conflict-free)
            ull c1 = *(const ull*)(crow + 32);   // +16 codes
            ull c2 = *(const ull*)(crow + 64);
            ull c3 = *(const ull*)(crow + 96);
            acc[0][0] = fma2(xA.x, c0, acc[0][0]);
            acc[0][1] = fma2(xA.x, c1, acc[0][1]);
            acc[0][2] = fma2(xA.x, c2, acc[0][2]);
            acc[0][3] = fma2(xA.x, c3, acc[0][3]);
            acc[1][0] = fma2(xA.y, c0, acc[1][0]);
            acc[1][1] = fma2(xA.y, c1, acc[1][1]);
            acc[1][2] = fma2(xA.y, c2, acc[1][2]);
            acc[1][3] = fma2(xA.y, c3, acc[1][3]);
            acc[2][0] = fma2(xB.x, c0, acc[2][0]);
            acc[2][1] = fma2(xB.x, c1, acc[2][1]);
            acc[2][2] = fma2(xB.x, c2, acc[2][2]);
            acc[2][3] = fma2(xB.x, c3, acc[2][3]);
            acc[3][0] = fma2(xB.y, c0, acc[3][0]);
            acc[3][1] = fma2(xB.y, c1, acc[3][1]);
            acc[3][2] = fma2(xB.y, c2, acc[3][2]);
            acc[3][3] = fma2(xB.y, c3, acc[3][3]);
            acc[4][0] = fma2(xC.x, c0, acc[4][0]);
            acc[4][1] = fma2(xC.x, c1, acc[4][1]);
            acc[4][2] = fma2(xC.x, c2, acc[4][2]);
            acc[4][3] = fma2(xC.x, c3, acc[4][3]);
            acc[5][0] = fma2(xC.y, c0, acc[5][0]);
            acc[5][1] = fma2(xC.y, c1, acc[5][1]);
            acc[5][2] = fma2(xC.y, c2, acc[5][2]);
            acc[5][3] = fma2(xC.y, c3, acc[5][3]);
            acc[6][0] = fma2(xD.x, c0, acc[6][0]);
            acc[6][1] = fma2(xD.x, c1, acc[6][1]);
            acc[6][2] = fma2(xD.x, c2, acc[6][2]);
            acc[6][3] = fma2(xD.x, c3, acc[6][3]);
            acc[7][0] = fma2(xD.y, c0, acc[7][0]);
            acc[7][1] = fma2(xD.y, c1, acc[7][1]);
            acc[7][2] = fma2(xD.y, c2, acc[7][2]);
            acc[7][3] = fma2(xD.y, c3, acc[7][3]);
        }

        // distances (reference add order) + running argmin.
        // per-thread visit order is k-ascending (j asc, lo=2k before hi=2k+1);
        // strict < keeps the lowest index.
        #pragma unroll
        for (int j = 0; j < 4; j++) {
            int   kp  = 2 * (j * 16 + hl);       // local lo code index
            int   k0  = kbase + kp;
            float cn0 = scn[kp];
            float cn1 = scn[kp + 1];
            #pragma unroll
            for (int r = 0; r < 8; r++) {
                float s0 = lo32(acc[r][j]);
                float s1 = hi32(acc[r][j]);
                float d0 = (xn[r] + cn0) - 2.f * s0;
                float d1 = (xn[r] + cn1) - 2.f * s1;
                if (d0 < bd[r]) { bd[r] = d0; bi[r] = k0; }
                if (d1 < bd[r]) { bd[r] = d1; bi[r] = k0 + 1; }
            }
        }
    }

    // ---- argmin reduce across the 16 colgrp lanes (tie -> lower index) ----
    #pragma unroll
    for (int i = 0; i < 8; i++) {
        float d = bd[i];
        int   b = bi[i];
        #pragma unroll
        for (int off = 8; off >= 1; off >>= 1) {
            float od = __shfl_xor_sync(0xffffffffu, d, off);
            int   ob = __shfl_xor_sync(0xffffffffu, b, off);
            if (od < d || (od == d && ob < b)) { d = od; b = ob; }
        }
        bd[i] = d;
        bi[i] = b;
    }

    // ---- epilogue: tokens, quantized_st, loss & usage partials ----
    float e_acc = 0.f, q_acc = 0.f;
    #pragma unroll
    for (int i = 0; i < 8; i++) {
        int row = row0 + rb + i;
        int b   = bi[i];
        if (hl == 0) {
            outt[row] = (float)b;
            atomicAdd(&g_counts[b], 1);
        }
        float4 q4 = *(const float4*)&cb[(size_t)b * D + hl * 4];
        float4 x4 = *(const float4*)&xin[(size_t)row * D + hl * 4];
        float t0 = q4.x - x4.x, t1 = q4.y - x4.y, t2 = q4.z - x4.z, t3 = q4.w - x4.w;
        float4 o;
        o.x = x4.x + t0; o.y = x4.y + t1; o.z = x4.z + t2; o.w = x4.w + t3;
        *(float4*)&outq[(size_t)row * D + hl * 4] = o;
        float e0 = o.x - x4.x, e1 = o.y - x4.y, e2 = o.z - x4.z, e3 = o.w - x4.w;
        e_acc += e0 * e0 + e1 * e1 + e2 * e2 + e3 * e3;
        q_acc += t0 * t0 + t1 * t1 + t2 * t2 + t3 * t3;
    }
    #pragma unroll
    for (int off = 16; off >= 1; off >>= 1) {
        e_acc += __shfl_xor_sync(0xffffffffu, e_acc, off);
        q_acc += __shfl_xor_sync(0xffffffffu, q_acc, off);
    }
    if (lane == 0) {
        atomicAdd(&g_loss[0], e_acc);
        atomicAdd(&g_loss[1], q_acc);
    }

    // ---- last-block finalize (4 scalars) + scratch reset for next replay ----
    __threadfence();
    __syncthreads();
    if (tid == 0) {
        unsigned t = atomicAdd(&g_done, 1u);
        s_last = (t == gridDim.x - 1) ? 1 : 0;
    }
    __syncthreads();
    if (s_last) {
        float h = 0.f;
        for (int k = tid; k < KCODES; k += NTHREADS) {
            float p = (float)g_counts[k] * invN;
            h += p * logf(p + 1e-10f);
        }
        sx2[tid] = h;
        __syncthreads();
        for (int s = NTHREADS / 2; s > 0; s >>= 1) {
            if (tid < s) sx2[tid] += sx2[tid + s];
            __syncthreads();
        }
        if (tid == 0) {
            float Le = g_loss[0] * inv_ND;
            float Lq = g_loss[1] * inv_ND;
            float commitment = 0.25f * Le;       // COMMITMENT_COST
            outs[0] = commitment + Lq;           // vq_loss
            outs[1] = commitment;                // commitment_loss
            outs[2] = Lq;                        // codebook_loss
            outs[3] = expf(-sx2[0]);             // perplexity
            g_loss[0] = 0.f;
            g_loss[1] = 0.f;
            g_done = 0u;
        }
        __syncthreads();
        for (int k = tid; k < KCODES; k += NTHREADS) g_counts[k] = 0;
    }
}

extern "C" void kernel_launch(void* const* d_in, const int* in_sizes, int n_in,
                              void* d_out, int out_size) {
    const float* x  = (const float*)d_in[0];
    const float* cb = (const float*)d_in[1];
    float* out = (float*)d_out;

    const int ND = in_sizes[0];       // N * D
    const int N  = ND / D;            // 262144

    float* outq = out;                // quantized_st, ND floats
    float* outt = out + ND;           // tokens (as float), N floats
    float* outs = out + ND + N;       // 4 scalars

    const int smem_bytes = (D * W2 + D * W3 + KC) * (int)sizeof(float);  // 100 KB
    cudaFuncSetAttribute(vq_fused, cudaFuncAttributeMaxDynamicSharedMemorySize, smem_bytes);

    vq_fused<<<N / MT, NTHREADS, smem_bytes>>>(x, cb, outq, outt, outs,
                                               1.f / (float)ND, 1.f / (float)N);
}